// round 1
// baseline (speedup 1.0000x reference)
#include <cuda_runtime.h>

// ---------------------------------------------------------------------------
// CorrelationModule: BN+ReLU+Conv3x3 -> channel L2 norm -> 9x9 dilated corr
// Shapes: x (4, 512, 64, 128) = 4 groups of 128ch; conv 128->128, pad 1.
// Output: (4, 3*81, 64, 128) fp32.
// ---------------------------------------------------------------------------

#define BB    4
#define GG    4      // feature groups
#define CI    128    // channels in (per group)
#define CO    128    // channels out
#define HH    64
#define WW    128
#define NIMG  16     // GG * BB
#define PATCH 9
#define DILP  2
#define PADC  8      // (PATCH/2)*DILP

// Scratch (device globals are the sanctioned scratch mechanism).
__device__ __align__(128) float g_nf[NIMG * HH * WW * CO];   // normalized feats, NHWC, 64 MiB
__device__ __align__(128) float g_wt2[CI * CO * 9];          // weights [cin][cout][tap]
__device__ float g_bn_a[CI];
__device__ float g_bn_b[CI];

// ---------------------------------------------------------------------------
// Prep: BN constant folding + weight transpose (coalesced writes)
// grid 576 x 256 = 147456 threads
// ---------------------------------------------------------------------------
__global__ void prep_kernel(const float* __restrict__ gamma,
                            const float* __restrict__ beta,
                            const float* __restrict__ mean,
                            const float* __restrict__ var,
                            const float* __restrict__ convw) {
    int idx = blockIdx.x * 256 + threadIdx.x;
    if (blockIdx.x == 0 && threadIdx.x < CI) {
        int c = threadIdx.x;
        float a = gamma[c] * rsqrtf(var[c] + 1e-5f);
        g_bn_a[c] = a;
        g_bn_b[c] = beta[c] - mean[c] * a;
    }
    if (idx < CI * CO * 9) {
        int t   = idx % 9;
        int rc  = idx / 9;
        int co  = rc % CO;
        int cin = rc / CO;
        // g_wt2[(cin*CO+co)*9+t] = convw[(co*CI+cin)*9+t]
        g_wt2[idx] = convw[(co * CI + cin) * 9 + t];
    }
}

// ---------------------------------------------------------------------------
// Conv: fused BN+ReLU (on load) + 3x3 conv + channel-L2 normalize (on store).
// One block per (row h, image). 256 threads = 16 w-groups x 16 cout-groups.
// Thread computes 8 w x 8 cout. cin processed in chunks of 4 through smem.
// ---------------------------------------------------------------------------
#define CCHUNK 4

__global__ __launch_bounds__(256, 2)
void conv_kernel(const float* __restrict__ x) {
    const int h   = blockIdx.x;      // 0..63
    const int img = blockIdx.y;      // 0..15  (img = g*4 + b)
    const int g   = img >> 2;
    const int b   = img & 3;

    const int tid = threadIdx.x;
    const int cg  = tid >> 4;        // cout group 0..15
    const int wg  = tid & 15;        // w group 0..15
    const int co0 = cg * 8;
    const int w0  = wg * 8;

    // smem: ws[4][128][12] (24KB) + xs[4][3][132] (6.2KB)
    __shared__ float smem[CCHUNK * CO * 12 + CCHUNK * 3 * 132];
    float* ws = smem;                        // [ci][co][12]
    float* xs = smem + CCHUNK * CO * 12;     // [ci][dy][132], wp in [0,129], w = wp-1

    float acc[8][8];
#pragma unroll
    for (int i = 0; i < 8; i++)
#pragma unroll
        for (int j = 0; j < 8; j++) acc[i][j] = 0.f;

    for (int cc = 0; cc < CI; cc += CCHUNK) {
        __syncthreads();
        // ---- load input rows h-1..h+1 for 4 cins, BN+ReLU applied, zero-pad
        for (int i = tid; i < CCHUNK * 3 * 130; i += 256) {
            int ci = i / 390;
            int r  = i - ci * 390;
            int dy = r / 130;
            int wp = r - dy * 130;
            int row = h + dy - 1;
            int w   = wp - 1;
            float v = 0.f;
            if ((unsigned)row < (unsigned)HH && (unsigned)w < (unsigned)WW) {
                int cin = cc + ci;
                float xv = x[(((b * (GG * CI)) + g * CI + cin) * HH + row) * WW + w];
                v = fmaxf(fmaf(xv, g_bn_a[cin], g_bn_b[cin]), 0.f);
            }
            xs[(ci * 3 + dy) * 132 + wp] = v;
        }
        // ---- load weights [ci][co][9] (padded stride 12)
        for (int i = tid; i < CCHUNK * CO * 9; i += 256) {
            int ci = i / (CO * 9);
            int r  = i - ci * (CO * 9);
            int co = r / 9;
            int t  = r - co * 9;
            ws[(ci * CO + co) * 12 + t] = g_wt2[(cc + ci) * (CO * 9) + r];
        }
        __syncthreads();

        // ---- compute
#pragma unroll
        for (int ci = 0; ci < CCHUNK; ci++) {
            float xr[3][10];
#pragma unroll
            for (int dy = 0; dy < 3; dy++) {
                const float* p = &xs[(ci * 3 + dy) * 132 + w0];
                float4 a0 = *reinterpret_cast<const float4*>(p);
                float4 a1 = *reinterpret_cast<const float4*>(p + 4);
                float2 a2 = *reinterpret_cast<const float2*>(p + 8);
                xr[dy][0] = a0.x; xr[dy][1] = a0.y; xr[dy][2] = a0.z; xr[dy][3] = a0.w;
                xr[dy][4] = a1.x; xr[dy][5] = a1.y; xr[dy][6] = a1.z; xr[dy][7] = a1.w;
                xr[dy][8] = a2.x; xr[dy][9] = a2.y;
            }
#pragma unroll
            for (int coi = 0; coi < 8; coi++) {
                const float* wp = &ws[(ci * CO + co0 + coi) * 12];
                float4 wa = *reinterpret_cast<const float4*>(wp);
                float4 wb = *reinterpret_cast<const float4*>(wp + 4);
                float  wc = wp[8];
                float wv0 = wa.x, wv1 = wa.y, wv2 = wa.z;
                float wv3 = wa.w, wv4 = wb.x, wv5 = wb.y;
                float wv6 = wb.z, wv7 = wb.w, wv8 = wc;
#pragma unroll
                for (int wi = 0; wi < 8; wi++) {
                    float s = acc[wi][coi];
                    s = fmaf(xr[0][wi    ], wv0, s);
                    s = fmaf(xr[0][wi + 1], wv1, s);
                    s = fmaf(xr[0][wi + 2], wv2, s);
                    s = fmaf(xr[1][wi    ], wv3, s);
                    s = fmaf(xr[1][wi + 1], wv4, s);
                    s = fmaf(xr[1][wi + 2], wv5, s);
                    s = fmaf(xr[2][wi    ], wv6, s);
                    s = fmaf(xr[2][wi + 1], wv7, s);
                    s = fmaf(xr[2][wi + 2], wv8, s);
                    acc[wi][coi] = s;
                }
            }
        }
    }

    // ---- channel L2 norm across the block (each w needs all 128 couts)
    __syncthreads();
    float* red = smem;  // reuse: [16 cout-groups][128 w]
    float ss[8];
#pragma unroll
    for (int wi = 0; wi < 8; wi++) {
        float s = 0.f;
#pragma unroll
        for (int coi = 0; coi < 8; coi++) s = fmaf(acc[wi][coi], acc[wi][coi], s);
        ss[wi] = s;
    }
#pragma unroll
    for (int wi = 0; wi < 8; wi++) red[cg * WW + w0 + wi] = ss[wi];
    __syncthreads();

#pragma unroll
    for (int wi = 0; wi < 8; wi++) {
        float n2 = 0.f;
#pragma unroll
        for (int k = 0; k < 16; k++) n2 += red[k * WW + w0 + wi];
        float inv = rsqrtf(n2);
        float* dst = &g_nf[(((img * HH) + h) * WW + (w0 + wi)) * CO + co0];
        float4 o0 = make_float4(acc[wi][0] * inv, acc[wi][1] * inv,
                                acc[wi][2] * inv, acc[wi][3] * inv);
        float4 o1 = make_float4(acc[wi][4] * inv, acc[wi][5] * inv,
                                acc[wi][6] * inv, acc[wi][7] * inv);
        *reinterpret_cast<float4*>(dst)     = o0;
        *reinterpret_cast<float4*>(dst + 4) = o1;
    }
}

// ---------------------------------------------------------------------------
// Correlation: out[b, pair*81 + py*9+px, h, w] =
//   sum_c nf1[b,h,w,c] * nf2[b, h+(py*2-8), w+(px*2-8), c]  (zero OOB)
// Block = (h, pair*4+b). 144 threads = 9 py x 16 w-groups; thread: 8w x 9px.
// f2 staged in smem [py][c][col] so compute loads are contiguous LDS.128.
// ---------------------------------------------------------------------------
#define CK 8

__global__ __launch_bounds__(144)
void corr_kernel(float* __restrict__ out) {
    const int h    = blockIdx.x;          // 0..63
    const int pb   = blockIdx.y;          // 0..11
    const int pair = pb >> 2;
    const int b    = pb & 3;
    const int img1 = pair * 4 + b;
    const int img2 = img1 + 4;

    const int tid = threadIdx.x;          // 0..143
    const int py  = tid / 16;             // 0..8
    const int wg  = tid - py * 16;        // 0..15
    const int w0  = wg * 8;

    __shared__ float f2s[PATCH][CK][148]; // [py][c][col], col = w2+8 in [0,143]
    __shared__ float f1s[CK][132];        // [c][w]

    float acc[8][PATCH];
#pragma unroll
    for (int i = 0; i < 8; i++)
#pragma unroll
        for (int j = 0; j < PATCH; j++) acc[i][j] = 0.f;

    for (int cch = 0; cch < CO / CK; cch++) {
        const int c0 = cch * CK;
        __syncthreads();
        // f1: 128 w x 8 c  (float4 over c)
        for (int i = tid; i < WW * CK / 4; i += 144) {
            int w  = i >> 1;
            int c4 = (i & 1) * 4;
            float4 v = *reinterpret_cast<const float4*>(
                &g_nf[(((img1 * HH) + h) * WW + w) * CO + c0 + c4]);
            f1s[c4 + 0][w] = v.x;
            f1s[c4 + 1][w] = v.y;
            f1s[c4 + 2][w] = v.z;
            f1s[c4 + 3][w] = v.w;
        }
        // f2: 9 rows x 144 cols x 8 c
        for (int i = tid; i < PATCH * 144 * CK / 4; i += 144) {
            int py2 = i / 288;
            int r   = i - py2 * 288;
            int col = r >> 1;
            int c4  = (r & 1) * 4;
            int row = h + py2 * 2 - PADC;
            int w2  = col - PADC;
            float4 v = make_float4(0.f, 0.f, 0.f, 0.f);
            if ((unsigned)row < (unsigned)HH && (unsigned)w2 < (unsigned)WW) {
                v = *reinterpret_cast<const float4*>(
                    &g_nf[(((img2 * HH) + row) * WW + w2) * CO + c0 + c4]);
            }
            f2s[py2][c4 + 0][col] = v.x;
            f2s[py2][c4 + 1][col] = v.y;
            f2s[py2][c4 + 2][col] = v.z;
            f2s[py2][c4 + 3][col] = v.w;
        }
        __syncthreads();

#pragma unroll
        for (int c = 0; c < CK; c++) {
            float f1v[8];
            {
                const float* p = &f1s[c][w0];
                float4 a0 = *reinterpret_cast<const float4*>(p);
                float4 a1 = *reinterpret_cast<const float4*>(p + 4);
                f1v[0] = a0.x; f1v[1] = a0.y; f1v[2] = a0.z; f1v[3] = a0.w;
                f1v[4] = a1.x; f1v[5] = a1.y; f1v[6] = a1.z; f1v[7] = a1.w;
            }
            float f2v[24];
            {
                const float* p = &f2s[py][c][w0];
#pragma unroll
                for (int q = 0; q < 6; q++) {
                    float4 v = *reinterpret_cast<const float4*>(p + q * 4);
                    f2v[q * 4 + 0] = v.x; f2v[q * 4 + 1] = v.y;
                    f2v[q * 4 + 2] = v.z; f2v[q * 4 + 3] = v.w;
                }
            }
#pragma unroll
            for (int wi = 0; wi < 8; wi++)
#pragma unroll
                for (int px = 0; px < PATCH; px++)
                    acc[wi][px] = fmaf(f1v[wi], f2v[wi + 2 * px], acc[wi][px]);
        }
    }

    // ---- write out: for each px, 8 consecutive w -> 2 x float4
#pragma unroll
    for (int px = 0; px < PATCH; px++) {
        int ch = pair * (PATCH * PATCH) + py * PATCH + px;
        float* dst = &out[(((b * (3 * PATCH * PATCH)) + ch) * HH + h) * WW + w0];
        float4 o0 = make_float4(acc[0][px], acc[1][px], acc[2][px], acc[3][px]);
        float4 o1 = make_float4(acc[4][px], acc[5][px], acc[6][px], acc[7][px]);
        *reinterpret_cast<float4*>(dst)     = o0;
        *reinterpret_cast<float4*>(dst + 4) = o1;
    }
}

// ---------------------------------------------------------------------------
extern "C" void kernel_launch(void* const* d_in, const int* in_sizes, int n_in,
                              void* d_out, int out_size) {
    const float* x     = (const float*)d_in[0];
    const float* gamma = (const float*)d_in[1];
    const float* beta  = (const float*)d_in[2];
    const float* mean  = (const float*)d_in[3];
    const float* var   = (const float*)d_in[4];
    const float* convw = (const float*)d_in[5];
    float* out = (float*)d_out;

    prep_kernel<<<576, 256>>>(gamma, beta, mean, var, convw);
    conv_kernel<<<dim3(HH, NIMG), 256>>>(x);
    corr_kernel<<<dim3(HH, 3 * BB), 144>>>(out);
}